// round 2
// baseline (speedup 1.0000x reference)
#include <cuda_runtime.h>
#include <cstdint>

#define N_NODES 100000
#define N_PAIRS 640000
#define F_TOTAL 128
#define N_HEADS 8
#define HEAD_DIM 16

// projected q,k,v in (node, head*16+e) layout
__device__ float g_q[N_NODES * F_TOTAL];
__device__ float g_k[N_NODES * F_TOTAL];
__device__ float g_v[N_NODES * F_TOTAL];

// CSR-by-idx_i machinery (rebuilt every launch; deterministic work)
__device__ int g_cnt[N_NODES];      // degree of node i
__device__ int g_rowptr[N_NODES];   // exclusive prefix of g_cnt
__device__ int g_cursor[N_NODES];   // running write cursor (copy of rowptr)
__device__ int g_perm[N_PAIRS];     // pair ids grouped by idx_i
#define NB1 98                       // ceil(100000/1024)
__device__ int g_bsum[NB1];

// Padded per-head stride in shared: 260 floats -> conflict-free float4 broadcast
#define W_STRIDE 260

__global__ void __launch_bounds__(256) proj_kernel(
    const float* __restrict__ x,
    const float* __restrict__ wq,
    const float* __restrict__ wk,
    const float* __restrict__ wv)
{
    __shared__ float sq[N_HEADS * W_STRIDE];
    __shared__ float sk[N_HEADS * W_STRIDE];
    __shared__ float sv[N_HEADS * W_STRIDE];

    for (int i = threadIdx.x; i < N_HEADS * HEAD_DIM * HEAD_DIM; i += 256) {
        int h = i >> 8;
        int r = i & 255;
        sq[h * W_STRIDE + r] = wq[i];
        sk[h * W_STRIDE + r] = wk[i];
        sv[h * W_STRIDE + r] = wv[i];
    }
    __syncthreads();

    int gid = blockIdx.x * 256 + threadIdx.x;   // gid = node*8 + head
    if (gid >= N_NODES * N_HEADS) return;
    int n = gid >> 3;
    int h = gid & 7;

    const float4* xp = reinterpret_cast<const float4*>(x + (size_t)n * F_TOTAL + h * HEAD_DIM);
    float4 xv0 = xp[0], xv1 = xp[1], xv2 = xp[2], xv3 = xp[3];
    float xr[16] = {xv0.x, xv0.y, xv0.z, xv0.w,
                    xv1.x, xv1.y, xv1.z, xv1.w,
                    xv2.x, xv2.y, xv2.z, xv2.w,
                    xv3.x, xv3.y, xv3.z, xv3.w};

    const float4* wq4 = reinterpret_cast<const float4*>(sq + h * W_STRIDE);
    const float4* wk4 = reinterpret_cast<const float4*>(sk + h * W_STRIDE);
    const float4* wv4 = reinterpret_cast<const float4*>(sv + h * W_STRIDE);

    float qo[16], ko[16], vo[16];
#pragma unroll
    for (int e = 0; e < 16; e++) {
        float aq = 0.f, ak = 0.f, av = 0.f;
#pragma unroll
        for (int d4 = 0; d4 < 4; d4++) {
            float4 a = wq4[e * 4 + d4];
            float4 b = wk4[e * 4 + d4];
            float4 c = wv4[e * 4 + d4];
            float x0 = xr[4 * d4 + 0], x1 = xr[4 * d4 + 1];
            float x2 = xr[4 * d4 + 2], x3 = xr[4 * d4 + 3];
            aq += x0 * a.x + x1 * a.y + x2 * a.z + x3 * a.w;
            ak += x0 * b.x + x1 * b.y + x2 * b.z + x3 * b.w;
            av += x0 * c.x + x1 * c.y + x2 * c.z + x3 * c.w;
        }
        qo[e] = aq; ko[e] = ak; vo[e] = av;
    }

    size_t base = (size_t)n * F_TOTAL + h * HEAD_DIM;
    float4* qdst = reinterpret_cast<float4*>(g_q + base);
    float4* kdst = reinterpret_cast<float4*>(g_k + base);
    float4* vdst = reinterpret_cast<float4*>(g_v + base);
#pragma unroll
    for (int i = 0; i < 4; i++) {
        qdst[i] = make_float4(qo[4*i], qo[4*i+1], qo[4*i+2], qo[4*i+3]);
        kdst[i] = make_float4(ko[4*i], ko[4*i+1], ko[4*i+2], ko[4*i+3]);
        vdst[i] = make_float4(vo[4*i], vo[4*i+1], vo[4*i+2], vo[4*i+3]);
    }
}

__global__ void __launch_bounds__(256) zero_cnt_kernel()
{
    int i = blockIdx.x * 256 + threadIdx.x;
    if (i < N_NODES) g_cnt[i] = 0;
}

__global__ void __launch_bounds__(256) hist_kernel(const int* __restrict__ idx_i)
{
    int p = blockIdx.x * 256 + threadIdx.x;
    if (p < N_PAIRS) atomicAdd(&g_cnt[idx_i[p]], 1);
}

// per-block (1024-element) exclusive scan of g_cnt into g_rowptr; block totals to g_bsum
__global__ void __launch_bounds__(256) scan1_kernel()
{
    __shared__ int sh[256];
    int t = threadIdx.x;
    int base = blockIdx.x * 1024 + t * 4;
    int v0 = (base + 0 < N_NODES) ? g_cnt[base + 0] : 0;
    int v1 = (base + 1 < N_NODES) ? g_cnt[base + 1] : 0;
    int v2 = (base + 2 < N_NODES) ? g_cnt[base + 2] : 0;
    int v3 = (base + 3 < N_NODES) ? g_cnt[base + 3] : 0;
    int s = v0 + v1 + v2 + v3;
    sh[t] = s;
    __syncthreads();
    for (int off = 1; off < 256; off <<= 1) {
        int add = (t >= off) ? sh[t - off] : 0;
        __syncthreads();
        sh[t] += add;
        __syncthreads();
    }
    int excl = sh[t] - s;
    if (base + 0 < N_NODES) g_rowptr[base + 0] = excl;
    if (base + 1 < N_NODES) g_rowptr[base + 1] = excl + v0;
    if (base + 2 < N_NODES) g_rowptr[base + 2] = excl + v0 + v1;
    if (base + 3 < N_NODES) g_rowptr[base + 3] = excl + v0 + v1 + v2;
    if (t == 255) g_bsum[blockIdx.x] = sh[255];
}

// exclusive scan of the NB1 block sums (single block)
__global__ void __launch_bounds__(128) scan2_kernel()
{
    __shared__ int sh[128];
    int t = threadIdx.x;
    int v = (t < NB1) ? g_bsum[t] : 0;
    sh[t] = v;
    __syncthreads();
    for (int off = 1; off < 128; off <<= 1) {
        int add = (t >= off) ? sh[t - off] : 0;
        __syncthreads();
        sh[t] += add;
        __syncthreads();
    }
    if (t < NB1) g_bsum[t] = sh[t] - v;
}

// add block offsets; duplicate into cursor
__global__ void __launch_bounds__(256) scan3_kernel()
{
    int i = blockIdx.x * 256 + threadIdx.x;
    if (i < N_NODES) {
        int v = g_rowptr[i] + g_bsum[i >> 10];
        g_rowptr[i] = v;
        g_cursor[i] = v;
    }
}

__global__ void __launch_bounds__(256) scatter_kernel(const int* __restrict__ idx_i)
{
    int p = blockIdx.x * 256 + threadIdx.x;
    if (p < N_PAIRS) {
        int i = idx_i[p];
        int pos = atomicAdd(&g_cursor[i], 1);
        g_perm[pos] = p;
    }
}

// One warp per node: q loaded once, loop over the node's pairs, store out once.
__global__ void __launch_bounds__(256) aggregate_kernel(
    const float* __restrict__ w_ij,
    const int*   __restrict__ idx_j,
    const float* __restrict__ phi,
    float*       __restrict__ out)
{
    int node = blockIdx.x * 8 + (threadIdx.x >> 5);
    if (node >= N_NODES) return;
    int lane = threadIdx.x & 31;

    int start = g_rowptr[node];
    int end = start + g_cnt[node];

    float4 q = reinterpret_cast<const float4*>(g_q)[(size_t)node * 32 + lane];
    float4 acc = make_float4(0.f, 0.f, 0.f, 0.f);

    int p = 0, j = 0; float ph = 0.f;
    if (start < end) {
        p = g_perm[start];
        j = idx_j[p];
        ph = phi[p];
    }
    for (int e = start; e < end; e++) {
        int cp = p, cj = j; float cph = ph;
        if (e + 1 < end) {                 // prefetch next pair's metadata
            p = g_perm[e + 1];
            j = idx_j[p];
            ph = phi[p];
        }
        float4 w = reinterpret_cast<const float4*>(w_ij)[(size_t)cp * 32 + lane];
        float4 k = reinterpret_cast<const float4*>(g_k)[(size_t)cj * 32 + lane];
        float4 v = reinterpret_cast<const float4*>(g_v)[(size_t)cj * 32 + lane];

        float part = q.x * w.x * k.x + q.y * w.y * k.y
                   + q.z * w.z * k.z + q.w * w.w * k.w;
        part += __shfl_xor_sync(0xFFFFFFFFu, part, 1);
        part += __shfl_xor_sync(0xFFFFFFFFu, part, 2);

        float alpha = part * 0.25f * cph;   // 1/sqrt(16)
        acc.x += alpha * v.x;
        acc.y += alpha * v.y;
        acc.z += alpha * v.z;
        acc.w += alpha * v.w;
    }
    reinterpret_cast<float4*>(out)[(size_t)node * 32 + lane] = acc;
}

extern "C" void kernel_launch(void* const* d_in, const int* in_sizes, int n_in,
                              void* d_out, int out_size)
{
    const float* x      = (const float*)d_in[0];
    const float* w_ij   = (const float*)d_in[1];
    const int*   idx_i  = (const int*)  d_in[2];
    const int*   idx_j  = (const int*)  d_in[3];
    const float* phi    = (const float*)d_in[4];
    const float* wq     = (const float*)d_in[5];
    const float* wk     = (const float*)d_in[6];
    const float* wv     = (const float*)d_in[7];
    float* out = (float*)d_out;

    // q/k/v projections
    proj_kernel<<<(N_NODES * N_HEADS + 255) / 256, 256>>>(x, wq, wk, wv);

    // build CSR (group pairs by idx_i)
    zero_cnt_kernel<<<(N_NODES + 255) / 256, 256>>>();
    hist_kernel<<<(N_PAIRS + 255) / 256, 256>>>(idx_i);
    scan1_kernel<<<NB1, 256>>>();
    scan2_kernel<<<1, 128>>>();
    scan3_kernel<<<(N_NODES + 255) / 256, 256>>>();
    scatter_kernel<<<(N_PAIRS + 255) / 256, 256>>>(idx_i);

    // gather-aggregate: one warp per node, single store per output row
    aggregate_kernel<<<(N_NODES + 7) / 8, 256>>>(w_ij, idx_j, phi, out);
}

// round 4
// speedup vs baseline: 1.1064x; 1.1064x over previous
#include <cuda_runtime.h>
#include <cstdint>

#define N_NODES 100000
#define N_PAIRS 640000
#define F_TOTAL 128
#define N_HEADS 8
#define HEAD_DIM 16

// projected q in (node, 128) layout; k & v interleaved per node: 256 floats
// per node, k at +0, v at +128.
__device__ float g_q [N_NODES * F_TOTAL];
__device__ float g_kv[N_NODES * F_TOTAL * 2];

// CSR-by-idx_i machinery (rebuilt every launch; deterministic work)
__device__ int  g_cnt[N_NODES];
__device__ int  g_rowptr[N_NODES];
__device__ int  g_cursor[N_NODES];
__device__ int4 g_meta[N_PAIRS];     // {pair_id, idx_j, phi_bits, 0} grouped by idx_i
#define NB1 98                       // ceil(100000/1024)
__device__ int g_bsum[NB1];

#define W_STRIDE 260

__global__ void __launch_bounds__(256) proj_kernel(
    const float* __restrict__ x,
    const float* __restrict__ wq,
    const float* __restrict__ wk,
    const float* __restrict__ wv)
{
    __shared__ float sq[N_HEADS * W_STRIDE];
    __shared__ float sk[N_HEADS * W_STRIDE];
    __shared__ float sv[N_HEADS * W_STRIDE];

    for (int i = threadIdx.x; i < N_HEADS * HEAD_DIM * HEAD_DIM; i += 256) {
        int h = i >> 8;
        int r = i & 255;
        sq[h * W_STRIDE + r] = wq[i];
        sk[h * W_STRIDE + r] = wk[i];
        sv[h * W_STRIDE + r] = wv[i];
    }
    __syncthreads();

    int gid = blockIdx.x * 256 + threadIdx.x;   // node*8 + head
    if (gid >= N_NODES * N_HEADS) return;
    int n = gid >> 3;
    int h = gid & 7;

    const float4* xp = reinterpret_cast<const float4*>(x + (size_t)n * F_TOTAL + h * HEAD_DIM);
    float4 xv0 = xp[0], xv1 = xp[1], xv2 = xp[2], xv3 = xp[3];
    float xr[16] = {xv0.x, xv0.y, xv0.z, xv0.w,
                    xv1.x, xv1.y, xv1.z, xv1.w,
                    xv2.x, xv2.y, xv2.z, xv2.w,
                    xv3.x, xv3.y, xv3.z, xv3.w};

    const float4* wq4 = reinterpret_cast<const float4*>(sq + h * W_STRIDE);
    const float4* wk4 = reinterpret_cast<const float4*>(sk + h * W_STRIDE);
    const float4* wv4 = reinterpret_cast<const float4*>(sv + h * W_STRIDE);

    float qo[16], ko[16], vo[16];
#pragma unroll
    for (int e = 0; e < 16; e++) {
        float aq = 0.f, ak = 0.f, av = 0.f;
#pragma unroll
        for (int d4 = 0; d4 < 4; d4++) {
            float4 a = wq4[e * 4 + d4];
            float4 b = wk4[e * 4 + d4];
            float4 c = wv4[e * 4 + d4];
            float x0 = xr[4 * d4 + 0], x1 = xr[4 * d4 + 1];
            float x2 = xr[4 * d4 + 2], x3 = xr[4 * d4 + 3];
            aq += x0 * a.x + x1 * a.y + x2 * a.z + x3 * a.w;
            ak += x0 * b.x + x1 * b.y + x2 * b.z + x3 * b.w;
            av += x0 * c.x + x1 * c.y + x2 * c.z + x3 * c.w;
        }
        qo[e] = aq; ko[e] = ak; vo[e] = av;
    }

    float4* qdst = reinterpret_cast<float4*>(g_q + (size_t)n * F_TOTAL + h * HEAD_DIM);
    float4* kdst = reinterpret_cast<float4*>(g_kv + (size_t)n * F_TOTAL * 2 + h * HEAD_DIM);
    float4* vdst = reinterpret_cast<float4*>(g_kv + (size_t)n * F_TOTAL * 2 + F_TOTAL + h * HEAD_DIM);
#pragma unroll
    for (int i = 0; i < 4; i++) {
        qdst[i] = make_float4(qo[4*i], qo[4*i+1], qo[4*i+2], qo[4*i+3]);
        kdst[i] = make_float4(ko[4*i], ko[4*i+1], ko[4*i+2], ko[4*i+3]);
        vdst[i] = make_float4(vo[4*i], vo[4*i+1], vo[4*i+2], vo[4*i+3]);
    }
}

__global__ void __launch_bounds__(256) zero_cnt_kernel()
{
    int i = blockIdx.x * 256 + threadIdx.x;
    if (i < N_NODES) g_cnt[i] = 0;
}

__global__ void __launch_bounds__(256) hist_kernel(const int* __restrict__ idx_i)
{
    int p = blockIdx.x * 256 + threadIdx.x;
    if (p < N_PAIRS) atomicAdd(&g_cnt[idx_i[p]], 1);
}

__global__ void __launch_bounds__(256) scan1_kernel()
{
    __shared__ int sh[256];
    int t = threadIdx.x;
    int base = blockIdx.x * 1024 + t * 4;
    int v0 = (base + 0 < N_NODES) ? g_cnt[base + 0] : 0;
    int v1 = (base + 1 < N_NODES) ? g_cnt[base + 1] : 0;
    int v2 = (base + 2 < N_NODES) ? g_cnt[base + 2] : 0;
    int v3 = (base + 3 < N_NODES) ? g_cnt[base + 3] : 0;
    int s = v0 + v1 + v2 + v3;
    sh[t] = s;
    __syncthreads();
    for (int off = 1; off < 256; off <<= 1) {
        int add = (t >= off) ? sh[t - off] : 0;
        __syncthreads();
        sh[t] += add;
        __syncthreads();
    }
    int excl = sh[t] - s;
    if (base + 0 < N_NODES) g_rowptr[base + 0] = excl;
    if (base + 1 < N_NODES) g_rowptr[base + 1] = excl + v0;
    if (base + 2 < N_NODES) g_rowptr[base + 2] = excl + v0 + v1;
    if (base + 3 < N_NODES) g_rowptr[base + 3] = excl + v0 + v1 + v2;
    if (t == 255) g_bsum[blockIdx.x] = sh[255];
}

__global__ void __launch_bounds__(128) scan2_kernel()
{
    __shared__ int sh[128];
    int t = threadIdx.x;
    int v = (t < NB1) ? g_bsum[t] : 0;
    sh[t] = v;
    __syncthreads();
    for (int off = 1; off < 128; off <<= 1) {
        int add = (t >= off) ? sh[t - off] : 0;
        __syncthreads();
        sh[t] += add;
        __syncthreads();
    }
    if (t < NB1) g_bsum[t] = sh[t] - v;
}

__global__ void __launch_bounds__(256) scan3_kernel()
{
    int i = blockIdx.x * 256 + threadIdx.x;
    if (i < N_NODES) {
        int v = g_rowptr[i] + g_bsum[i >> 10];
        g_rowptr[i] = v;
        g_cursor[i] = v;
    }
}

// scatter full metadata record so the aggregate loop has a single-hop chain
__global__ void __launch_bounds__(256) scatter_kernel(
    const int* __restrict__ idx_i,
    const int* __restrict__ idx_j,
    const float* __restrict__ phi)
{
    int p = blockIdx.x * 256 + threadIdx.x;
    if (p < N_PAIRS) {
        int i = idx_i[p];
        int pos = atomicAdd(&g_cursor[i], 1);
        g_meta[pos] = make_int4(p, idx_j[p], __float_as_int(phi[p]), 0);
    }
}

// One warp per node, depth-2 software pipeline, no atomics, one store per row.
__global__ void __launch_bounds__(256) aggregate_kernel(
    const float* __restrict__ w_ij,
    float*       __restrict__ out)
{
    int node = blockIdx.x * 8 + (threadIdx.x >> 5);
    if (node >= N_NODES) return;
    int lane = threadIdx.x & 31;

    int start = g_rowptr[node];
    int deg   = g_cnt[node];

    const float4* w4  = reinterpret_cast<const float4*>(w_ij);
    const float4* kv4 = reinterpret_cast<const float4*>(g_kv);

    float4 q = reinterpret_cast<const float4*>(g_q)[(size_t)node * 32 + lane];
    float4 acc = make_float4(0.f, 0.f, 0.f, 0.f);

    float4 wA, kA, vA, wB, kB, vB;
    float phA = 0.f, phB = 0.f;

    if (deg > 0) {
        int4 m = g_meta[start];
        phA = __int_as_float(m.z);
        wA = __ldcs(w4 + (size_t)m.x * 32 + lane);               // streaming
        kA = __ldg(kv4 + (size_t)m.y * 64 + lane);
        vA = __ldg(kv4 + (size_t)m.y * 64 + 32 + lane);
    }
    if (deg > 1) {
        int4 m = g_meta[start + 1];
        phB = __int_as_float(m.z);
        wB = __ldcs(w4 + (size_t)m.x * 32 + lane);
        kB = __ldg(kv4 + (size_t)m.y * 64 + lane);
        vB = __ldg(kv4 + (size_t)m.y * 64 + 32 + lane);
    }

    for (int e = 0; e < deg; e++) {
        float4 wc = wA, kc = kA, vc = vA; float phc = phA;
        // rotate: B -> A, prefetch e+2 -> B  (two iterations of slack)
        wA = wB; kA = kB; vA = vB; phA = phB;
        if (e + 2 < deg) {
            int4 m = g_meta[start + e + 2];
            phB = __int_as_float(m.z);
            wB = __ldcs(w4 + (size_t)m.x * 32 + lane);
            kB = __ldg(kv4 + (size_t)m.y * 64 + lane);
            vB = __ldg(kv4 + (size_t)m.y * 64 + 32 + lane);
        }
        float part = q.x * wc.x * kc.x + q.y * wc.y * kc.y
                   + q.z * wc.z * kc.z + q.w * wc.w * kc.w;
        part += __shfl_xor_sync(0xFFFFFFFFu, part, 1);
        part += __shfl_xor_sync(0xFFFFFFFFu, part, 2);

        float alpha = part * 0.25f * phc;   // 1/sqrt(16)
        acc.x += alpha * vc.x;
        acc.y += alpha * vc.y;
        acc.z += alpha * vc.z;
        acc.w += alpha * vc.w;
    }
    reinterpret_cast<float4*>(out)[(size_t)node * 32 + lane] = acc;
}

extern "C" void kernel_launch(void* const* d_in, const int* in_sizes, int n_in,
                              void* d_out, int out_size)
{
    const float* x      = (const float*)d_in[0];
    const float* w_ij   = (const float*)d_in[1];
    const int*   idx_i  = (const int*)  d_in[2];
    const int*   idx_j  = (const int*)  d_in[3];
    const float* phi    = (const float*)d_in[4];
    const float* wq     = (const float*)d_in[5];
    const float* wk     = (const float*)d_in[6];
    const float* wv     = (const float*)d_in[7];
    float* out = (float*)d_out;

    proj_kernel<<<(N_NODES * N_HEADS + 255) / 256, 256>>>(x, wq, wk, wv);

    zero_cnt_kernel<<<(N_NODES + 255) / 256, 256>>>();
    hist_kernel<<<(N_PAIRS + 255) / 256, 256>>>(idx_i);
    scan1_kernel<<<NB1, 256>>>();
    scan2_kernel<<<1, 128>>>();
    scan3_kernel<<<(N_NODES + 255) / 256, 256>>>();
    scatter_kernel<<<(N_PAIRS + 255) / 256, 256>>>(idx_i, idx_j, phi);

    aggregate_kernel<<<(N_NODES + 7) / 8, 256>>>(w_ij, out);
}